// round 12
// baseline (speedup 1.0000x reference)
#include <cuda_runtime.h>
#include <cuda_bf16.h>
#include <cstdint>

#define BB 4
#define NN 4096
#define CC 256
#define CK 32

// bf16 hi/lo split scratch (device globals = legal scratch)
__device__ __nv_bfloat16 d_Fhi[BB * NN * CK], d_Flo[BB * NN * CK];
__device__ __nv_bfloat16 d_Ghi[BB * NN * CK], d_Glo[BB * NN * CK];
__device__ __nv_bfloat16 d_Hhi[(size_t)BB * NN * CC], d_Hlo[(size_t)BB * NN * CC];

// ------------------------- helpers -------------------------
__device__ __forceinline__ uint32_t smem_u32(const void* p) {
    uint32_t a;
    asm("{ .reg .u64 t; cvta.to.shared.u64 t, %1; cvt.u32.u64 %0, t; }" : "=r"(a) : "l"(p));
    return a;
}
__device__ __forceinline__ void ldsm4(uint32_t* r, uint32_t a) {
    asm volatile("ldmatrix.sync.aligned.m8n8.x4.shared.b16 {%0,%1,%2,%3}, [%4];"
        : "=r"(r[0]), "=r"(r[1]), "=r"(r[2]), "=r"(r[3]) : "r"(a));
}
__device__ __forceinline__ void ldsm4t(uint32_t* r, uint32_t a) {
    asm volatile("ldmatrix.sync.aligned.m8n8.x4.trans.shared.b16 {%0,%1,%2,%3}, [%4];"
        : "=r"(r[0]), "=r"(r[1]), "=r"(r[2]), "=r"(r[3]) : "r"(a));
}
__device__ __forceinline__ void mma_bf16(float* d, const uint32_t* a, uint32_t b0, uint32_t b1) {
    asm volatile("mma.sync.aligned.m16n8k16.row.col.f32.bf16.bf16.f32 "
        "{%0,%1,%2,%3}, {%4,%5,%6,%7}, {%8,%9}, {%0,%1,%2,%3};"
        : "+f"(d[0]), "+f"(d[1]), "+f"(d[2]), "+f"(d[3])
        : "r"(a[0]), "r"(a[1]), "r"(a[2]), "r"(a[3]), "r"(b0), "r"(b1));
}
__device__ __forceinline__ void cpasync16(uint32_t saddr, const void* g) {
    asm volatile("cp.async.cg.shared.global [%0], [%1], 16;" :: "r"(saddr), "l"(g));
}
#define CP_COMMIT() asm volatile("cp.async.commit_group;")
#define CP_WAIT0()  asm volatile("cp.async.wait_group 0;" ::: "memory")
#define STS32(a, v) asm volatile("st.shared.b32 [%0], %1;" :: "r"(a), "r"(v) : "memory")

__device__ __forceinline__ void bsplit(float v, __nv_bfloat16& hi, __nv_bfloat16& lo) {
    hi = __float2bfloat16(v);
    lo = __float2bfloat16(v - __bfloat162float(hi));
}
__device__ __forceinline__ uint32_t pkbf(float a, float b) {
    return ((uint32_t)__bfloat16_as_ushort(__float2bfloat16(b)) << 16) |
           (uint32_t)__bfloat16_as_ushort(__float2bfloat16(a));
}

// ---- flash4 smem layout (bytes). G/F pitch 80, P pitch 48, H pitch 528 ----
#define OFF_G    0        // 32 rows: hi +0, lo +2560           (5120)
#define OFF_P    5120     // + pbuf*3072; hi +0, lo +1536       (6144)
#define OFF_LRED 11264    // 32 floats                          (128)
#define OFF_F    11392    // + fbuf*2560; hi +0, lo +1280       (7680, 3 bufs)
#define OFF_H    19072    // + hbuf*16896; hi +0, lo +8448      (50688, 3 bufs)
#define SMEM4    69760

// =====================================================================
// Kernel 1: projections -> bf16 hi/lo splits (unchanged)
// =====================================================================
__global__ __launch_bounds__(256) void proj_kernel(
    const float* __restrict__ x,
    const float* __restrict__ Wf, const float* __restrict__ bfv,
    const float* __restrict__ Wg, const float* __restrict__ bgv,
    const float* __restrict__ Wh, const float* __restrict__ bhv)
{
    __shared__ float xs[64][64];
    __shared__ float ws[64][64];

    const int t = threadIdx.x;
    const int pix0 = blockIdx.x * 64;
    const int pg = t >> 4;
    const int og = t & 15;

    for (int oc = 0; oc < 5; oc++) {
        float acc[4][4];
#pragma unroll
        for (int i = 0; i < 4; i++)
#pragma unroll
            for (int j = 0; j < 4; j++) acc[i][j] = 0.f;

        for (int kc = 0; kc < 4; kc++) {
            __syncthreads();
            for (int i = t; i < 1024; i += 256) {
                int px = i >> 4;
                int kq = i & 15;
                *(float4*)&xs[px][kq * 4] =
                    *(const float4*)&x[(size_t)(pix0 + px) * CC + kc * 64 + kq * 4];
            }
            for (int i = t; i < 4096; i += 256) {
                int k = i >> 6;
                int o = i & 63;
                int kg = kc * 64 + k;
                float v;
                if (oc == 0)
                    v = (o < 32) ? Wf[kg * CK + o] : Wg[kg * CK + (o - 32)];
                else
                    v = Wh[kg * CC + (oc - 1) * 64 + o];
                ws[k][o] = v;
            }
            __syncthreads();

#pragma unroll 8
            for (int k = 0; k < 64; k++) {
                float4 wv = *(const float4*)&ws[k][og * 4];
                float xv0 = xs[pg * 4 + 0][k];
                float xv1 = xs[pg * 4 + 1][k];
                float xv2 = xs[pg * 4 + 2][k];
                float xv3 = xs[pg * 4 + 3][k];
                acc[0][0] += xv0 * wv.x; acc[0][1] += xv0 * wv.y;
                acc[0][2] += xv0 * wv.z; acc[0][3] += xv0 * wv.w;
                acc[1][0] += xv1 * wv.x; acc[1][1] += xv1 * wv.y;
                acc[1][2] += xv1 * wv.z; acc[1][3] += xv1 * wv.w;
                acc[2][0] += xv2 * wv.x; acc[2][1] += xv2 * wv.y;
                acc[2][2] += xv2 * wv.z; acc[2][3] += xv2 * wv.w;
                acc[3][0] += xv3 * wv.x; acc[3][1] += xv3 * wv.y;
                acc[3][2] += xv3 * wv.z; acc[3][3] += xv3 * wv.w;
            }
        }

#pragma unroll
        for (int i = 0; i < 4; i++) {
            int px = pix0 + pg * 4 + i;
#pragma unroll
            for (int j = 0; j < 4; j++) {
                int o = og * 4 + j;
                __nv_bfloat16 hi, lo;
                if (oc == 0) {
                    if (o < 32) {
                        bsplit(acc[i][j] + bfv[o], hi, lo);
                        d_Fhi[px * CK + o] = hi; d_Flo[px * CK + o] = lo;
                    } else {
                        bsplit(acc[i][j] + bgv[o - 32], hi, lo);
                        d_Ghi[px * CK + o - 32] = hi; d_Glo[px * CK + o - 32] = lo;
                    }
                } else {
                    int oo = (oc - 1) * 64 + o;
                    bsplit(acc[i][j] + bhv[oo], hi, lo);
                    d_Hhi[(size_t)px * CC + oo] = hi; d_Hlo[(size_t)px * CC + oo] = lo;
                }
            }
        }
    }
}

// =====================================================================
// tile loader (256 threads): F (16x32 hi/lo) + H (16x256 hi/lo), JT=16
// =====================================================================
__device__ __forceinline__ void load_tile(uint32_t sb, int buf, size_t bpix, int j0, int t)
{
    uint32_t hb = sb + OFF_H + buf * 16896;
#pragma unroll
    for (int i = 0; i < 4; i++) {
        int id = t + 256 * i;
        int hl = id >> 9, r = (id >> 5) & 15, c = id & 31;
        const __nv_bfloat16* s = (hl ? d_Hlo : d_Hhi) + (bpix + j0 + r) * CC + c * 8;
        cpasync16(hb + hl * 8448 + (uint32_t)r * 528 + c * 16, s);
    }
    if (t < 128) {
        int hl = t >> 6, r = (t >> 2) & 15, c = t & 3;
        const __nv_bfloat16* s = (hl ? d_Flo : d_Fhi) + (bpix + j0 + r) * CK + c * 8;
        cpasync16(sb + OFF_F + buf * 2560 + hl * 1280 + (uint32_t)r * 80 + c * 16, s);
    }
}

// =====================================================================
// Kernel 2: flash4. CTA = 32 q, 8 warps (256 thr), JT=16, 256 tiles.
// 2 CTAs/SM (anti-phased barriers keep tensor pipe fed).
// QK (warps 0-3): warp = (16q mt=w&1) x (8j n8=w>>1).
// PV (all 8):     warp = 32q x 32ch (cb=w*32), lagged by one tile.
// One __syncthreads per tile; F/H triple-buffered, P double-buffered.
// =====================================================================
__global__ __launch_bounds__(256, 2) void flash4(
    const float* __restrict__ x, float* __restrict__ out)
{
    extern __shared__ char sm[];
    const uint32_t sb = smem_u32(sm);
    const int t = threadIdx.x;
    const int w = t >> 5, l = t & 31;
    const int b = blockIdx.x >> 7, qt = blockIdx.x & 127;
    const size_t bpix = (size_t)b * NN;
    const size_t qpix = bpix + qt * 32;
    const int sel = l >> 3;
    const int mt = w & 1, n8 = w >> 1;      // QK mapping (warps 0-3)
    const int cb = w * 32;                  // PV channel base

    // prologue: G (32q x 32k hi/lo) + tile 0
    {
        int hl = t >> 7, r = (t >> 2) & 31, c = t & 3;
        const __nv_bfloat16* s = (hl ? d_Glo : d_Ghi) + (qpix + r) * CK + c * 8;
        cpasync16(sb + OFF_G + hl * 2560 + (uint32_t)r * 80 + c * 16, s);
    }
    load_tile(sb, 0, bpix, 0, t);
    CP_COMMIT();
    CP_WAIT0();
    __syncthreads();

    float* lred = (float*)(sm + OFF_LRED);
    if (t < 32) lred[t] = 0.f;

    // persistent G A-fragments (warps 0-3): rows mt*16..+15, k 0..31
    uint32_t aGh[2][4], aGl[2][4];
    if (w < 4) {
#pragma unroll
        for (int ks = 0; ks < 2; ks++) {
            uint32_t roff = (uint32_t)(mt * 16 + (sel & 1) * 8 + (l & 7)) * 80 +
                            ks * 32 + (sel >> 1) * 16;
            ldsm4(aGh[ks], sb + OFF_G + roff);
            ldsm4(aGl[ks], sb + OFF_G + 2560 + roff);
        }
    }

    float O[2][4][4];
#pragma unroll
    for (int i = 0; i < 2; i++)
#pragma unroll
        for (int j = 0; j < 4; j++)
#pragma unroll
            for (int k = 0; k < 4; k++) O[i][j][k] = 0.f;
    float lacc0 = 0.f, lacc1 = 0.f;

    const uint32_t qk_roff = (uint32_t)(n8 * 8 + (l & 7)) * 80 + sel * 16;
    const uint32_t p_colb  = (uint32_t)(n8 * 8 + (l & 3) * 2) * 2;
    const int p_r0 = mt * 16 + (l >> 2);

#pragma unroll 1
    for (int tile = 0; tile < 256; tile++) {
        CP_WAIT0();          // tile data landed
        __syncthreads();     // visible to all; P[tile-1] visible; prior readers done
        if (tile + 1 < 256) {
            load_tile(sb, (tile + 1) % 3, bpix, (tile + 1) * 16, t);
            CP_COMMIT();
        }

        // ---- QK(tile): warps 0-3, S[16q x 8j] ----
        float d[4] = {0.f, 0.f, 0.f, 0.f};
        if (w < 4) {
            uint32_t fb = sb + OFF_F + (tile % 3) * 2560;
            uint32_t bFh[4], bFl[4];
            ldsm4(bFh, fb + qk_roff);
            ldsm4(bFl, fb + 1280 + qk_roff);
#pragma unroll
            for (int ks = 0; ks < 2; ks++) {
                mma_bf16(d, aGh[ks], bFh[ks * 2], bFh[ks * 2 + 1]);
                mma_bf16(d, aGh[ks], bFl[ks * 2], bFl[ks * 2 + 1]);
                mma_bf16(d, aGl[ks], bFh[ks * 2], bFh[ks * 2 + 1]);
            }
        }

        // ---- PV(tile-1): all warps, O[32q x 32ch] += P . H ----
        if (tile > 0) {
            uint32_t hb = sb + OFF_H + ((tile - 1) % 3) * 16896;
            uint32_t pbase = sb + OFF_P + ((tile - 1) & 1) * 3072;
            uint32_t bHh[2][4], bHl[2][4];
#pragma unroll
            for (int ntp = 0; ntp < 2; ntp++) {
                uint32_t roff = (uint32_t)((sel & 1) * 8 + (l & 7)) * 528 +
                                cb * 2 + ntp * 32 + (sel >> 1) * 16;
                ldsm4t(bHh[ntp], hb + roff);
                ldsm4t(bHl[ntp], hb + 8448 + roff);
            }
#pragma unroll
            for (int m2 = 0; m2 < 2; m2++) {
                uint32_t aPh[4], aPl[4];
                uint32_t roff = (uint32_t)(m2 * 16 + (sel & 1) * 8 + (l & 7)) * 48 +
                                (sel >> 1) * 16;
                ldsm4(aPh, pbase + roff);
                ldsm4(aPl, pbase + 1536 + roff);
#pragma unroll
                for (int nt = 0; nt < 4; nt++) {
                    int ntp = nt >> 1, o2 = (nt & 1) * 2;
                    mma_bf16(O[m2][nt], aPh, bHh[ntp][o2], bHh[ntp][o2 + 1]);
                    mma_bf16(O[m2][nt], aPh, bHl[ntp][o2], bHl[ntp][o2 + 1]);
                    mma_bf16(O[m2][nt], aPl, bHh[ntp][o2], bHh[ntp][o2 + 1]);
                }
            }
        }

        // ---- exp(tile) -> P[tile&1] (warps 0-3) ----
        if (w < 4) {
            float e0 = __expf(d[0]), e1 = __expf(d[1]);
            float e2 = __expf(d[2]), e3 = __expf(d[3]);
            lacc0 += e0 + e1; lacc1 += e2 + e3;
            __nv_bfloat16 h0 = __float2bfloat16(e0), h1 = __float2bfloat16(e1);
            __nv_bfloat16 h2 = __float2bfloat16(e2), h3 = __float2bfloat16(e3);
            uint32_t pb = sb + OFF_P + (tile & 1) * 3072;
            STS32(pb + (uint32_t)p_r0 * 48 + p_colb,
                  ((uint32_t)__bfloat16_as_ushort(h1) << 16) | __bfloat16_as_ushort(h0));
            STS32(pb + (uint32_t)(p_r0 + 8) * 48 + p_colb,
                  ((uint32_t)__bfloat16_as_ushort(h3) << 16) | __bfloat16_as_ushort(h2));
            STS32(pb + 1536 + (uint32_t)p_r0 * 48 + p_colb,
                  pkbf(e0 - __bfloat162float(h0), e1 - __bfloat162float(h1)));
            STS32(pb + 1536 + (uint32_t)(p_r0 + 8) * 48 + p_colb,
                  pkbf(e2 - __bfloat162float(h2), e3 - __bfloat162float(h3)));
        }
    }

    // ---- final PV(255) ----
    __syncthreads();
    {
        uint32_t hb = sb + OFF_H + (255 % 3) * 16896;
        uint32_t pbase = sb + OFF_P + (255 & 1) * 3072;
        uint32_t bHh[2][4], bHl[2][4];
#pragma unroll
        for (int ntp = 0; ntp < 2; ntp++) {
            uint32_t roff = (uint32_t)((sel & 1) * 8 + (l & 7)) * 528 +
                            cb * 2 + ntp * 32 + (sel >> 1) * 16;
            ldsm4t(bHh[ntp], hb + roff);
            ldsm4t(bHl[ntp], hb + 8448 + roff);
        }
#pragma unroll
        for (int m2 = 0; m2 < 2; m2++) {
            uint32_t aPh[4], aPl[4];
            uint32_t roff = (uint32_t)(m2 * 16 + (sel & 1) * 8 + (l & 7)) * 48 +
                            (sel >> 1) * 16;
            ldsm4(aPh, pbase + roff);
            ldsm4(aPl, pbase + 1536 + roff);
#pragma unroll
            for (int nt = 0; nt < 4; nt++) {
                int ntp = nt >> 1, o2 = (nt & 1) * 2;
                mma_bf16(O[m2][nt], aPh, bHh[ntp][o2], bHh[ntp][o2 + 1]);
                mma_bf16(O[m2][nt], aPh, bHl[ntp][o2], bHl[ntp][o2 + 1]);
                mma_bf16(O[m2][nt], aPl, bHh[ntp][o2], bHh[ntp][o2 + 1]);
            }
        }
    }

    // ---- l reduction (warps 0-3): quad shuffle + atomic ----
    if (w < 4) {
        lacc0 += __shfl_xor_sync(0xffffffffu, lacc0, 1);
        lacc0 += __shfl_xor_sync(0xffffffffu, lacc0, 2);
        lacc1 += __shfl_xor_sync(0xffffffffu, lacc1, 1);
        lacc1 += __shfl_xor_sync(0xffffffffu, lacc1, 2);
        if ((l & 3) == 0) {
            atomicAdd(&lred[mt * 16 + (l >> 2)], lacc0);
            atomicAdd(&lred[mt * 16 + (l >> 2) + 8], lacc1);
        }
    }
    __syncthreads();

    // ---- epilogue: normalize + residual ----
#pragma unroll
    for (int m2 = 0; m2 < 2; m2++) {
        int r0 = m2 * 16 + (l >> 2), r1 = r0 + 8;
        float i0 = 1.0f / lred[r0], i1 = 1.0f / lred[r1];
#pragma unroll
        for (int nt = 0; nt < 4; nt++) {
            int col = cb + nt * 8 + (l & 3) * 2;
            size_t p0 = (qpix + r0) * CC + col;
            size_t p1 = (qpix + r1) * CC + col;
            float2 xv0 = *(const float2*)&x[p0];
            float2 xv1 = *(const float2*)&x[p1];
            float2 ov0, ov1;
            ov0.x = xv0.x + O[m2][nt][0] * i0;
            ov0.y = xv0.y + O[m2][nt][1] * i0;
            ov1.x = xv1.x + O[m2][nt][2] * i1;
            ov1.y = xv1.y + O[m2][nt][3] * i1;
            *(float2*)&out[p0] = ov0;
            *(float2*)&out[p1] = ov1;
        }
    }
}

// =====================================================================
extern "C" void kernel_launch(void* const* d_in, const int* in_sizes, int n_in,
                              void* d_out, int out_size)
{
    const float* x  = (const float*)d_in[0];
    const float* Wf = (const float*)d_in[1];
    const float* bf = (const float*)d_in[2];
    const float* Wg = (const float*)d_in[3];
    const float* bg = (const float*)d_in[4];
    const float* Wh = (const float*)d_in[5];
    const float* bh = (const float*)d_in[6];
    float* out = (float*)d_out;

    cudaFuncSetAttribute(flash4, cudaFuncAttributeMaxDynamicSharedMemorySize, SMEM4);

    proj_kernel<<<BB * NN / 64, 256>>>(x, Wf, bf, Wg, bg, Wh, bh);
    flash4<<<BB * NN / 32, 256, SMEM4>>>(x, out);
}